// round 6
// baseline (speedup 1.0000x reference)
#include <cuda_runtime.h>
#include <cuda_bf16.h>
#include <cstdint>
#include <cstddef>

// ---------------- problem constants ----------------
#define BATCH   4096
#define UNITS   1024
#define TSTEPS  128
#define BM      128            // batch rows per tile
#define BN      128            // z-cols per tile = 32 units * 4 gates
#define KCB     128            // K int8 bytes per chunk
#define NKC     8              // chunks over K=1024
#define ROWB    144            // padded smem row: 128B data + 16B pad (conflict-free ldsm)
#define PL_A    (128 * ROWB)   // 18432 B per plane (A1/A0/B1/B0 all 128 rows)
#define O_A1    0
#define O_A0    (PL_A)
#define O_B1    (2 * PL_A)
#define O_B0    (3 * PL_A)
#define STAGE   (4 * PL_A)     // 73728 B
#define NSTG    3
#define SMEM_DYN (NSTG * STAGE)   // 221184 B
#define HN      (4096UL * 1024UL)
#define ZLD     132            // epilogue z smem row stride (floats)
#define QSC     32256.0f       // quantization scale target (126*256)

// ---------------- device-global state ----------------
__device__ int8_t g_a1[2][HN];     // h hi limb (ping/pong) [4096][1024]
__device__ int8_t g_a0[2][HN];     // h lo limb
__device__ int8_t g_w1[HN];        // W hi limb, permuted [n=4u+g][k]
__device__ int8_t g_w0[HN];        // W lo limb
__device__ float  g_dq[2][BATCH];  // per-row h dequant:  h = (256*a1+a0)*dq
__device__ float  g_qw[4 * UNITS]; // per-col W dequant:  W = (256*w1+w0)*qw
__device__ float  g_c[HN];         // cell state fp32, in place
__device__ float  g_kp[4 * UNITS]; // permuted input kernel
__device__ float  g_bp[4 * UNITS]; // permuted bias
__device__ float  g_x[BATCH];      // autoregressive feedback input

// ---------------- small helpers ----------------
__device__ __forceinline__ uint32_t smem_u32(const void* p) {
    uint32_t a;
    asm("{ .reg .u64 t; cvta.to.shared.u64 t, %1; cvt.u32.u64 %0, t; }" : "=r"(a) : "l"(p));
    return a;
}
__device__ __forceinline__ void cp16(uint32_t dst, const void* src) {
    asm volatile("cp.async.cg.shared.global [%0], [%1], 16;" :: "r"(dst), "l"(src) : "memory");
}
__device__ __forceinline__ void cp_commit() {
    asm volatile("cp.async.commit_group;" ::: "memory");
}
template <int N>
__device__ __forceinline__ void cp_wait() {
    asm volatile("cp.async.wait_group %0;" :: "n"(N) : "memory");
}
__device__ __forceinline__ void ldsm_x4(uint32_t addr, uint32_t* r) {
    asm volatile("ldmatrix.sync.aligned.m8n8.x4.shared.b16 {%0,%1,%2,%3}, [%4];"
                 : "=r"(r[0]), "=r"(r[1]), "=r"(r[2]), "=r"(r[3]) : "r"(addr));
}
__device__ __forceinline__ void mma_s8(int* d, const uint32_t* a, const uint32_t* b) {
    asm volatile(
        "mma.sync.aligned.m16n8k32.row.col.s32.s8.s8.s32 "
        "{%0,%1,%2,%3}, {%4,%5,%6,%7}, {%8,%9}, {%0,%1,%2,%3};"
        : "+r"(d[0]), "+r"(d[1]), "+r"(d[2]), "+r"(d[3])
        : "r"(a[0]), "r"(a[1]), "r"(a[2]), "r"(a[3]), "r"(b[0]), "r"(b[1]));
}
__device__ __forceinline__ float sigf(float x) {
    return __fdividef(1.0f, 1.0f + __expf(-x));
}
__device__ __forceinline__ float tanhf_(float x) {
    return __fdividef(2.0f, 1.0f + __expf(-2.0f * x)) - 1.0f;
}
__device__ __forceinline__ void quant2(float v, float scale, int8_t& q1, int8_t& q0) {
    float a = v * scale;
    int i1 = __float2int_rn(a * (1.0f / 256.0f));
    i1 = max(-127, min(127, i1));
    int i0 = __float2int_rn(a - 256.0f * (float)i1);
    i0 = max(-127, min(127, i0));
    q1 = (int8_t)i1;
    q0 = (int8_t)i0;
}

// ---------------- prep kernels ----------------
// One block per permuted output column n = 4u+g: per-col max, quantize to 2 limbs.
__global__ void prep_w_kernel(const float* __restrict__ W) {
    __shared__ float red[256];
    int n = blockIdx.x;
    int u = n >> 2, g = n & 3;
    int col = g * 1024 + u;
    float v[4];
    float mx = 0.0f;
    #pragma unroll
    for (int i = 0; i < 4; i++) {
        v[i] = W[(size_t)(threadIdx.x + 256 * i) * 4096 + col];
        mx = fmaxf(mx, fabsf(v[i]));
    }
    red[threadIdx.x] = mx;
    __syncthreads();
    for (int s = 128; s; s >>= 1) {
        if (threadIdx.x < s) red[threadIdx.x] = fmaxf(red[threadIdx.x], red[threadIdx.x + s]);
        __syncthreads();
    }
    float m = red[0];
    float scale = (m > 0.0f) ? (QSC / m) : 0.0f;
    #pragma unroll
    for (int i = 0; i < 4; i++) {
        int k = threadIdx.x + 256 * i;
        int8_t q1, q0;
        quant2(v[i], scale, q1, q0);
        g_w1[(size_t)n * 1024 + k] = q1;
        g_w0[(size_t)n * 1024 + k] = q0;
    }
    if (threadIdx.x == 0) g_qw[n] = (m > 0.0f) ? (m / QSC) : 0.0f;
}

__global__ void prep_small_kernel(const float* __restrict__ kern, const float* __restrict__ bias) {
    int idx = blockIdx.x * 256 + threadIdx.x;   // 0..4095
    int g = idx & 3, u = idx >> 2;
    int c = g * 1024 + u;
    g_kp[idx] = kern[c];
    g_bp[idx] = bias[c];
    g_x[idx] = 0.0f;
}

// One block per batch row: rowmax of |features|, quantize h0 (duplicated), set c0.
__global__ void init_hc_kernel(const float* __restrict__ feat) {
    __shared__ float red[512];
    int b = blockIdx.x, t = threadIdx.x;
    float f = feat[(size_t)b * 512 + (t & 511)];
    red[t] = fabsf(f);
    __syncthreads();
    for (int s = 256; s; s >>= 1) {
        if (t < s) red[t] = fmaxf(red[t], red[t + s]);
        __syncthreads();
    }
    float m = red[0];
    float scale = (m > 0.0f) ? (QSC / m) : 0.0f;
    #pragma unroll
    for (int rep = 0; rep < 2; rep++) {
        int u = t + 512 * rep;      // u & 511 == t & 511 -> same f
        size_t gi = (size_t)b * 1024 + u;
        int8_t q1, q0;
        quant2(f, scale, q1, q0);
        g_a1[0][gi] = q1;
        g_a0[0][gi] = q0;
        g_c[gi] = f;
    }
    if (t == 0) g_dq[0][b] = (m > 0.0f) ? (m / QSC) : 0.0f;
}

// pred[b] = h[b,:].dw + db with h = (256*a1+a0)*dq[b]; write out[b][t], feedback g_x[b]
__global__ void collect_kernel(const float* __restrict__ dw, const float* __restrict__ db,
                               float* __restrict__ out, int dst, int t) {
    int wid = threadIdx.x >> 5, lid = threadIdx.x & 31;
    int row = blockIdx.x * 8 + wid;
    const int8_t* a1 = g_a1[dst];
    const int8_t* a0 = g_a0[dst];
    size_t base = (size_t)row * 1024;
    float s = 0.0f;
    #pragma unroll
    for (int i = 0; i < 32; i++) {
        int u = i * 32 + lid;
        float h = 256.0f * (float)a1[base + u] + (float)a0[base + u];
        s += h * dw[u];
    }
    #pragma unroll
    for (int o = 16; o; o >>= 1) s += __shfl_down_sync(0xFFFFFFFFu, s, o);
    if (lid == 0) {
        float p = s * g_dq[dst][row] + db[0];
        out[(size_t)row * TSTEPS + t] = p;
        g_x[row] = p;
    }
}

// ---------------- fused LSTM step (int8 mma.sync engine) ----------------
__global__ void __launch_bounds__(512, 1)
step_kernel(int src) {
    extern __shared__ char sm[];
    const int tid = threadIdx.x;
    const int w = tid >> 5, l = tid & 31;
    const int dst = src ^ 1;
    const int mt = blockIdx.x & 31, nt = blockIdx.x >> 5;
    const int m0 = mt << 7;      // batch row base
    const int n0 = nt << 7;      // z col base (128 cols)
    const int u0 = nt << 5;      // unit base (32 units)

    const uint32_t sb = smem_u32(sm);

    // per-plane global bases for this tile
    const int8_t* bases[4] = {
        g_a1[src] + (size_t)m0 * 1024,
        g_a0[src] + (size_t)m0 * 1024,
        g_w1      + (size_t)n0 * 1024,
        g_w0      + (size_t)n0 * 1024
    };

    // warp tiling: 4 (m) x 4 (n); warp tile 32x32
    const int m_off = (w & 3) * 32;
    const int n_off = (w >> 2) * 32;

    int acc_h[2][4][4], acc_l[2][4][4];
    #pragma unroll
    for (int im = 0; im < 2; im++)
        #pragma unroll
        for (int jn = 0; jn < 4; jn++)
            #pragma unroll
            for (int q = 0; q < 4; q++) { acc_h[im][jn][q] = 0; acc_l[im][jn][q] = 0; }

    // -------- producer: load chunk kc into stage kc%3 (4096 x 16B, 8/thread) --------
    auto load_chunk = [&](int kc) {
        const uint32_t so = sb + (uint32_t)(kc % 3) * STAGE;
        const int k0 = kc * KCB;
        #pragma unroll
        for (int i = 0; i < 8; i++) {
            int o = tid + i * 512;       // 0..4095
            int plane = o >> 10;         // 0:A1 1:A0 2:B1 3:B0
            int idx = o & 1023;
            int row = idx >> 3, seg = idx & 7;
            uint32_t d = so + plane * PL_A + row * ROWB + seg * 16;
            const int8_t* s = bases[plane] + (size_t)row * 1024 + k0 + seg * 16;
            cp16(d, s);
        }
        cp_commit();
    };

    // ldmatrix address helpers (byte-identical geometry to validated bf16 path)
    auto a_addr = [&](uint32_t base, int im, int ks) -> uint32_t {
        int row = m_off + im * 16 + (l & 15);
        int byte = ks * 32 + ((l >> 4) * 16);
        return base + row * ROWB + byte;
    };
    auto b_addr = [&](uint32_t base, int jn2, int ks) -> uint32_t {
        int row = n_off + jn2 * 16 + (l & 7) + ((l >> 4) << 3);
        int byte = ks * 32 + (((l >> 3) & 1) * 16);
        return base + row * ROWB + byte;
    };

    // -------- 3-stage pipeline, one sync per chunk --------
    load_chunk(0);
    load_chunk(1);
    for (int kc = 0; kc < NKC; kc++) {
        cp_wait<1>();
        __syncthreads();
        const uint32_t so = sb + (uint32_t)(kc % 3) * STAGE;
        #pragma unroll
        for (int ks = 0; ks < 4; ks++) {
            uint32_t a1f[2][4], a0f[2][4], bf[8];
            #pragma unroll
            for (int im = 0; im < 2; im++) ldsm_x4(a_addr(so + O_A1, im, ks), a1f[im]);
            #pragma unroll
            for (int im = 0; im < 2; im++) ldsm_x4(a_addr(so + O_A0, im, ks), a0f[im]);
            // B hi limb
            #pragma unroll
            for (int jn2 = 0; jn2 < 2; jn2++) ldsm_x4(b_addr(so + O_B1, jn2, ks), &bf[jn2 * 4]);
            #pragma unroll
            for (int im = 0; im < 2; im++)
                #pragma unroll
                for (int jn = 0; jn < 4; jn++)
                    mma_s8(acc_h[im][jn], a1f[im], &bf[(jn >> 1) * 4 + (jn & 1) * 2]);
            #pragma unroll
            for (int im = 0; im < 2; im++)
                #pragma unroll
                for (int jn = 0; jn < 4; jn++)
                    mma_s8(acc_l[im][jn], a0f[im], &bf[(jn >> 1) * 4 + (jn & 1) * 2]);
            // B lo limb (reuse bf)
            #pragma unroll
            for (int jn2 = 0; jn2 < 2; jn2++) ldsm_x4(b_addr(so + O_B0, jn2, ks), &bf[jn2 * 4]);
            #pragma unroll
            for (int im = 0; im < 2; im++)
                #pragma unroll
                for (int jn = 0; jn < 4; jn++)
                    mma_s8(acc_l[im][jn], a1f[im], &bf[(jn >> 1) * 4 + (jn & 1) * 2]);
        }
        if (kc + 2 < NKC) load_chunk(kc + 2);
    }

    __syncthreads();

    // -------- epilogue: combine limbs -> smem z, fuse gates --------
    float* zs = (float*)sm;   // [128][ZLD] fp32
    #pragma unroll
    for (int im = 0; im < 2; im++) {
        int m = m_off + im * 16 + (l >> 2);
        #pragma unroll
        for (int jn = 0; jn < 4; jn++) {
            int n = n_off + jn * 8 + (l & 3) * 2;
            float z0 = 65536.0f * (float)acc_h[im][jn][0] + 256.0f * (float)acc_l[im][jn][0];
            float z1 = 65536.0f * (float)acc_h[im][jn][1] + 256.0f * (float)acc_l[im][jn][1];
            float z2 = 65536.0f * (float)acc_h[im][jn][2] + 256.0f * (float)acc_l[im][jn][2];
            float z3 = 65536.0f * (float)acc_h[im][jn][3] + 256.0f * (float)acc_l[im][jn][3];
            *(float2*)&zs[m * ZLD + n]       = make_float2(z0, z1);
            *(float2*)&zs[(m + 8) * ZLD + n] = make_float2(z2, z3);
        }
    }
    __syncthreads();

    {
        const int u = tid & 31;        // unit within tile (0..31)
        const int r0 = tid >> 5;       // 0..15
        const int n = n0 + 4 * u;
        const float4 kp4 = *(const float4*)&g_kp[n];
        const float4 bp4 = *(const float4*)&g_bp[n];
        const float4 qw4 = *(const float4*)&g_qw[n];
        const float inv_dq = 1.0f / QSC;
        #pragma unroll 2
        for (int i = 0; i < 8; i++) {
            int r = r0 + 16 * i;
            int row = m0 + r;
            float xr = g_x[row];
            float dqm = g_dq[src][row];
            float4 z4 = *(const float4*)&zs[r * ZLD + 4 * u];
            float zi = z4.x * (dqm * qw4.x) + xr * kp4.x + bp4.x;
            float zf = z4.y * (dqm * qw4.y) + xr * kp4.y + bp4.y;
            float zg = z4.z * (dqm * qw4.z) + xr * kp4.z + bp4.z;
            float zo = z4.w * (dqm * qw4.w) + xr * kp4.w + bp4.w;
            size_t gi = (size_t)row * 1024 + u0 + u;
            float co = g_c[gi];
            float iv = sigf(zi), fv = sigf(zf);
            float gv = tanhf_(zg), ov = sigf(zo);
            float cn = fv * co + iv * gv;
            float hn = ov * tanhf_(cn);
            g_c[gi] = cn;
            int8_t q1, q0;
            quant2(hn, QSC, q1, q0);   // |hn| < 1 guaranteed
            g_a1[dst][gi] = q1;
            g_a0[dst][gi] = q0;
            if (u == 0 && nt == 0) g_dq[dst][row] = inv_dq;
        }
    }
}

// ---------------- host side ----------------
extern "C" void kernel_launch(void* const* d_in, const int* in_sizes, int n_in,
                              void* d_out, int out_size) {
    const float* features = (const float*)d_in[0];
    const float* kern     = (const float*)d_in[1];
    const float* W        = (const float*)d_in[2];
    const float* bias     = (const float*)d_in[3];
    const float* dw       = (const float*)d_in[4];
    const float* db       = (const float*)d_in[5];
    float* out = (float*)d_out;

    cudaFuncSetAttribute(step_kernel, cudaFuncAttributeMaxDynamicSharedMemorySize, SMEM_DYN);

    prep_w_kernel<<<4096, 256>>>(W);
    prep_small_kernel<<<16, 256>>>(kern, bias);
    init_hc_kernel<<<4096, 512>>>(features);

    for (int t = 0; t < TSTEPS; t++) {
        int src = t & 1;
        int dst = src ^ 1;
        step_kernel<<<1024, 512, SMEM_DYN>>>(src);
        collect_kernel<<<512, 256>>>(dw, db, out, dst, t);
    }
}

// round 7
// speedup vs baseline: 2.5162x; 2.5162x over previous
#include <cuda_runtime.h>
#include <cuda_bf16.h>
#include <cstdint>
#include <cstddef>

// ---------------- problem constants ----------------
#define BATCH   4096
#define UNITS   1024
#define TSTEPS  128
#define BM      128            // batch rows per tile
#define BN      128            // z-cols per tile = 32 units * 4 gates
#define KC      32             // K elements per chunk (64B rows)
#define NKC     32             // chunks over K=1024
#define ROWB    80             // padded smem row: 64B data + 16B pad (conflict-free ldsm)
#define PL      (128 * ROWB)   // 10240 B per plane (Ah/Al/Bh/Bl each 128 rows)
#define O_AH    0
#define O_AL    (PL)
#define O_BH    (2 * PL)
#define O_BL    (3 * PL)
#define STAGE   (4 * PL)       // 40960 B
#define SMEM_DYN (2 * STAGE)   // 81920 B  (2 CTAs/SM fit)
#define HN      (4096UL * 1024UL)
#define ZLD     132            // epilogue z smem row stride (floats)

// ---------------- device-global state ----------------
__device__ __nv_bfloat16 g_hh[2][HN];   // hidden hi (ping/pong)  [4096][1024]
__device__ __nv_bfloat16 g_hl[2][HN];   // hidden lo
__device__ __nv_bfloat16 g_Wh[HN * 4];  // permuted W hi: [n=4u+g][k]  (4096x1024)
__device__ __nv_bfloat16 g_Wl[HN * 4];  // permuted W lo
__device__ float         g_c[HN];       // cell state fp32, in place
__device__ float         g_kp[4 * UNITS];   // permuted input kernel
__device__ float         g_bp[4 * UNITS];   // permuted bias
__device__ float         g_x[BATCH];        // autoregressive feedback input

// ---------------- small helpers ----------------
__device__ __forceinline__ uint32_t smem_u32(const void* p) {
    uint32_t a;
    asm("{ .reg .u64 t; cvta.to.shared.u64 t, %1; cvt.u32.u64 %0, t; }" : "=r"(a) : "l"(p));
    return a;
}
__device__ __forceinline__ void cp16(uint32_t dst, const void* src) {
    asm volatile("cp.async.cg.shared.global [%0], [%1], 16;" :: "r"(dst), "l"(src) : "memory");
}
__device__ __forceinline__ void cp_commit() {
    asm volatile("cp.async.commit_group;" ::: "memory");
}
template <int N>
__device__ __forceinline__ void cp_wait() {
    asm volatile("cp.async.wait_group %0;" :: "n"(N) : "memory");
}
__device__ __forceinline__ void ldsm_x4(uint32_t addr, uint32_t* r) {
    asm volatile("ldmatrix.sync.aligned.m8n8.x4.shared.b16 {%0,%1,%2,%3}, [%4];"
                 : "=r"(r[0]), "=r"(r[1]), "=r"(r[2]), "=r"(r[3]) : "r"(addr));
}
__device__ __forceinline__ void mma_bf16(float* d, const uint32_t* a, const uint32_t* b) {
    asm volatile(
        "mma.sync.aligned.m16n8k16.row.col.f32.bf16.bf16.f32 "
        "{%0,%1,%2,%3}, {%4,%5,%6,%7}, {%8,%9}, {%0,%1,%2,%3};"
        : "+f"(d[0]), "+f"(d[1]), "+f"(d[2]), "+f"(d[3])
        : "r"(a[0]), "r"(a[1]), "r"(a[2]), "r"(a[3]), "r"(b[0]), "r"(b[1]));
}
__device__ __forceinline__ float sigf(float x) {
    return __fdividef(1.0f, 1.0f + __expf(-x));
}
__device__ __forceinline__ float tanhf_(float x) {
    return __fdividef(2.0f, 1.0f + __expf(-2.0f * x)) - 1.0f;
}

// ---------------- prep kernels ----------------
__global__ void prep_w_kernel(const float* __restrict__ W) {
    int u = blockIdx.x * 32 + threadIdx.x;
    int k = blockIdx.y * 8 + threadIdx.y;
    int g = blockIdx.z;
    float v = W[(size_t)k * 4096 + g * 1024 + u];
    __nv_bfloat16 hi = __float2bfloat16(v);
    float lo = v - __bfloat162float(hi);
    size_t o = ((size_t)(4 * u + g)) * 1024 + k;
    g_Wh[o] = hi;
    g_Wl[o] = __float2bfloat16(lo);
}

__global__ void prep_small_kernel(const float* __restrict__ kern, const float* __restrict__ bias) {
    int idx = blockIdx.x * 256 + threadIdx.x;   // 0..4095
    int g = idx & 3, u = idx >> 2;
    int c = g * 1024 + u;
    g_kp[idx] = kern[c];
    g_bp[idx] = bias[c];
    g_x[idx] = 0.0f;
}

__global__ void init_hc_kernel(const float* __restrict__ feat) {
    size_t idx = (size_t)blockIdx.x * 1024 + threadIdx.x;
    int b = blockIdx.x, u = threadIdx.x;
    float v = feat[(size_t)b * 512 + (u & 511)];
    __nv_bfloat16 hi = __float2bfloat16(v);
    float lo = v - __bfloat162float(hi);
    g_hh[0][idx] = hi;
    g_hl[0][idx] = __float2bfloat16(lo);
    g_c[idx] = v;
}

// pred[b] = (h_hi+h_lo)[b,:] . dw + db ; write out[b][t], feedback g_x[b]
__global__ void collect_kernel(const float* __restrict__ dw, const float* __restrict__ db,
                               float* __restrict__ out, int dst, int t) {
    int wid = threadIdx.x >> 5, lid = threadIdx.x & 31;
    int row = blockIdx.x * 8 + wid;
    const __nv_bfloat16* hh = g_hh[dst];
    const __nv_bfloat16* hl = g_hl[dst];
    size_t base = (size_t)row * 1024;
    float s = 0.0f;
    #pragma unroll
    for (int i = 0; i < 32; i++) {
        int u = i * 32 + lid;
        float h = __bfloat162float(hh[base + u]) + __bfloat162float(hl[base + u]);
        s += h * dw[u];
    }
    #pragma unroll
    for (int o = 16; o; o >>= 1) s += __shfl_down_sync(0xFFFFFFFFu, s, o);
    if (lid == 0) {
        float p = s + db[0];
        out[(size_t)row * TSTEPS + t] = p;
        g_x[row] = p;
    }
}

// ---------------- fused LSTM step (bf16 3-pass, 2 CTAs/SM) ----------------
__global__ void __launch_bounds__(256, 2)
step_kernel(int src) {
    extern __shared__ char sm[];
    const int tid = threadIdx.x;
    const int w = tid >> 5, l = tid & 31;
    const int dst = src ^ 1;
    const int mt = blockIdx.x & 31, nt = blockIdx.x >> 5;
    const int m0 = mt << 7;      // batch row base
    const int n0 = nt << 7;      // z col base (128 cols)
    const int u0 = nt << 5;      // unit base (32 units)

    const uint32_t sb = smem_u32(sm);

    // per-plane global row bases for this tile (row stride 2048 B)
    const char* bases[4] = {
        (const char*)(g_hh[src] + (size_t)m0 * 1024),
        (const char*)(g_hl[src] + (size_t)m0 * 1024),
        (const char*)(g_Wh      + (size_t)n0 * 1024),
        (const char*)(g_Wl      + (size_t)n0 * 1024)
    };

    // warp tiling: 4 (m) x 2 (n); warp tile 32x64
    const int m_off = (w & 3) * 32;
    const int n_off = (w >> 2) * 64;

    float acc[2][8][4];
    #pragma unroll
    for (int im = 0; im < 2; im++)
        #pragma unroll
        for (int jn = 0; jn < 8; jn++)
            #pragma unroll
            for (int q = 0; q < 4; q++) acc[im][jn][q] = 0.0f;

    // -------- producer: load chunk kc into stage kc&1 (2048 x 16B, 8/thread) --------
    auto load_chunk = [&](int kc) {
        const uint32_t so = sb + (uint32_t)(kc & 1) * STAGE;
        const int k0 = kc * KC;
        #pragma unroll
        for (int i = 0; i < 8; i++) {
            int o = tid + i * 256;       // 0..2047
            int plane = o >> 9;          // 0:Ah 1:Al 2:Bh 3:Bl (512 ops each)
            int idx = o & 511;
            int row = idx >> 2, seg = idx & 3;
            uint32_t d = so + plane * PL + row * ROWB + seg * 16;
            const char* s = bases[plane] + (size_t)row * 2048 + k0 * 2 + seg * 16;
            cp16(d, s);
        }
        cp_commit();
    };

    // ldmatrix address helpers (80B rows -> conflict-free phases)
    auto a_addr = [&](uint32_t base, int im, int ks) -> uint32_t {
        int row = m_off + im * 16 + (l & 15);
        int byte = ks * 32 + ((l >> 4) * 16);
        return base + row * ROWB + byte;
    };
    auto b_addr = [&](uint32_t base, int jn2, int ks) -> uint32_t {
        int row = n_off + jn2 * 16 + (l & 7) + ((l >> 4) << 3);
        int byte = ks * 32 + (((l >> 3) & 1) * 16);
        return base + row * ROWB + byte;
    };

    // -------- 2-stage pipeline --------
    load_chunk(0);
    load_chunk(1);
    for (int kc = 0; kc < NKC; kc++) {
        cp_wait<1>();
        __syncthreads();
        const uint32_t so = sb + (uint32_t)(kc & 1) * STAGE;
        #pragma unroll
        for (int ks = 0; ks < 2; ks++) {
            uint32_t ah[2][4], al[2][4], bb[16];
            #pragma unroll
            for (int im = 0; im < 2; im++) ldsm_x4(a_addr(so + O_AH, im, ks), ah[im]);
            #pragma unroll
            for (int im = 0; im < 2; im++) ldsm_x4(a_addr(so + O_AL, im, ks), al[im]);
            #pragma unroll
            for (int jn2 = 0; jn2 < 4; jn2++) ldsm_x4(b_addr(so + O_BH, jn2, ks), &bb[jn2 * 4]);
            // hi*hi and lo*hi against resident B_hi
            #pragma unroll
            for (int im = 0; im < 2; im++)
                #pragma unroll
                for (int jn = 0; jn < 8; jn++)
                    mma_bf16(acc[im][jn], ah[im], &bb[(jn >> 1) * 4 + (jn & 1) * 2]);
            #pragma unroll
            for (int im = 0; im < 2; im++)
                #pragma unroll
                for (int jn = 0; jn < 8; jn++)
                    mma_bf16(acc[im][jn], al[im], &bb[(jn >> 1) * 4 + (jn & 1) * 2]);
            // overwrite with B_lo, hi*lo
            #pragma unroll
            for (int jn2 = 0; jn2 < 4; jn2++) ldsm_x4(b_addr(so + O_BL, jn2, ks), &bb[jn2 * 4]);
            #pragma unroll
            for (int im = 0; im < 2; im++)
                #pragma unroll
                for (int jn = 0; jn < 8; jn++)
                    mma_bf16(acc[im][jn], ah[im], &bb[(jn >> 1) * 4 + (jn & 1) * 2]);
        }
        __syncthreads();
        if (kc + 2 < NKC) load_chunk(kc + 2);
    }

    // -------- epilogue: acc -> smem z, fuse gates --------
    float* zs = (float*)sm;   // [128][ZLD] fp32 (aliases stage memory; synced above)
    #pragma unroll
    for (int im = 0; im < 2; im++) {
        int m = m_off + im * 16 + (l >> 2);
        #pragma unroll
        for (int jn = 0; jn < 8; jn++) {
            int n = n_off + jn * 8 + (l & 3) * 2;
            *(float2*)&zs[m * ZLD + n]       = make_float2(acc[im][jn][0], acc[im][jn][1]);
            *(float2*)&zs[(m + 8) * ZLD + n] = make_float2(acc[im][jn][2], acc[im][jn][3]);
        }
    }
    __syncthreads();

    {
        const int u = tid & 31;        // unit within tile (0..31)
        const int r0 = tid >> 5;       // 0..7
        const int n = n0 + 4 * u;
        const float4 kp4 = *(const float4*)&g_kp[n];
        const float4 bp4 = *(const float4*)&g_bp[n];
        #pragma unroll 4
        for (int i = 0; i < 16; i++) {
            int r = r0 + 8 * i;
            int row = m0 + r;
            float xr = g_x[row];
            float4 z4 = *(const float4*)&zs[r * ZLD + 4 * u];
            float zi = z4.x + xr * kp4.x + bp4.x;
            float zf = z4.y + xr * kp4.y + bp4.y;
            float zg = z4.z + xr * kp4.z + bp4.z;
            float zo = z4.w + xr * kp4.w + bp4.w;
            size_t gi = (size_t)row * 1024 + u0 + u;
            float co = g_c[gi];
            float iv = sigf(zi), fv = sigf(zf);
            float gv = tanhf_(zg), ov = sigf(zo);
            float cn = fv * co + iv * gv;
            float hn = ov * tanhf_(cn);
            g_c[gi] = cn;
            __nv_bfloat16 hi = __float2bfloat16(hn);
            float lo = hn - __bfloat162float(hi);
            g_hh[dst][gi] = hi;
            g_hl[dst][gi] = __float2bfloat16(lo);
        }
    }
}

// ---------------- host side ----------------
extern "C" void kernel_launch(void* const* d_in, const int* in_sizes, int n_in,
                              void* d_out, int out_size) {
    const float* features = (const float*)d_in[0];
    const float* kern     = (const float*)d_in[1];
    const float* W        = (const float*)d_in[2];
    const float* bias     = (const float*)d_in[3];
    const float* dw       = (const float*)d_in[4];
    const float* db       = (const float*)d_in[5];
    float* out = (float*)d_out;

    cudaFuncSetAttribute(step_kernel, cudaFuncAttributeMaxDynamicSharedMemorySize, SMEM_DYN);

    prep_w_kernel<<<dim3(32, 128, 4), dim3(32, 8)>>>(W);
    prep_small_kernel<<<16, 256>>>(kern, bias);
    init_hc_kernel<<<4096, 1024>>>(features);

    for (int t = 0; t < TSTEPS; t++) {
        int src = t & 1;
        int dst = src ^ 1;
        step_kernel<<<1024, 256, SMEM_DYN>>>(src);
        collect_kernel<<<512, 256>>>(dw, db, out, dst, t);
    }
}